// round 13
// baseline (speedup 1.0000x reference)
#include <cuda_runtime.h>
#include <math.h>

#define SQ 4096
#define DMODEL 1024
#define NH 16
#define DH 64

// Scratch (allocation-free rule: __device__ globals)
__device__ float g_q[SQ * DMODEL];
__device__ float g_k[SQ * DMODEL];
__device__ float g_v[SQ * DMODEL];
__device__ float g_attn[SQ * DMODEL];
// bf16 split planes: X (row-major [r][k]) and W^T (n-major [which][n][k])
__device__ unsigned short g_xs0[SQ * DMODEL];
__device__ unsigned short g_xs1[SQ * DMODEL];
__device__ unsigned short g_xs2[SQ * DMODEL];
__device__ unsigned short g_ws0[3 * DMODEL * DMODEL];
__device__ unsigned short g_ws1[3 * DMODEL * DMODEL];
__device__ unsigned short g_ws2[3 * DMODEL * DMODEL];

// ---------------------------------------------------------------------------
// bf16 helpers — ONLY constructs already proven on this toolchain (R11):
// cvt.rn.bf16x2.f32 and mma.m16n8k16.bf16. No scalar bf16 cvt.
// ---------------------------------------------------------------------------
// pack {lo -> bits[15:0], hi -> bits[31:16]}
__device__ __forceinline__ unsigned bf2(float lo, float hi) {
    unsigned r;
    asm("cvt.rn.bf16x2.f32 %0, %1, %2;" : "=r"(r) : "f"(hi), "f"(lo));
    return r;
}
__device__ __forceinline__ unsigned short f2bf(float x) {
    return (unsigned short)(bf2(x, 0.f) & 0xFFFFu);
}
__device__ __forceinline__ float bf2f(unsigned short h) {
    return __uint_as_float((unsigned)h << 16);
}
__device__ __forceinline__ void mma_bf16(
    float& c0, float& c1, float& c2, float& c3,
    unsigned a0, unsigned a1, unsigned a2, unsigned a3,
    unsigned b0, unsigned b1)
{
    asm volatile(
        "mma.sync.aligned.m16n8k16.row.col.f32.bf16.bf16.f32 "
        "{%0,%1,%2,%3}, {%4,%5,%6,%7}, {%8,%9}, {%0,%1,%2,%3};"
        : "+f"(c0), "+f"(c1), "+f"(c2), "+f"(c3)
        : "r"(a0), "r"(a1), "r"(a2), "r"(a3), "r"(b0), "r"(b1));
}
__device__ __forceinline__ void split3(float x, unsigned short& b0,
                                       unsigned short& b1, unsigned short& b2) {
    b0 = f2bf(x);
    float r = x - bf2f(b0);
    b1 = f2bf(r);
    b2 = f2bf(r - bf2f(b1));
}

// ---------------------------------------------------------------------------
// P1: split X into 3 bf16 planes (same layout as X)
// ---------------------------------------------------------------------------
__global__ void prep_x(const float* __restrict__ X,
                       unsigned short* __restrict__ h0,
                       unsigned short* __restrict__ h1,
                       unsigned short* __restrict__ h2, int n)
{
    for (int i = blockIdx.x * 256 + threadIdx.x; i < n; i += gridDim.x * 256) {
        unsigned short b0, b1, b2;
        split3(X[i], b0, b1, b2);
        h0[i] = b0; h1[i] = b1; h2[i] = b2;
    }
}

// ---------------------------------------------------------------------------
// P2: split + TRANSPOSE one W [k][n] -> planes [n][k] (n-major, k contiguous)
// ---------------------------------------------------------------------------
__global__ void prep_wt(const float* __restrict__ W,
                        unsigned short* __restrict__ h0,
                        unsigned short* __restrict__ h1,
                        unsigned short* __restrict__ h2)
{
    __shared__ float t[32][33];
    const int n0 = blockIdx.x * 32, k0 = blockIdx.y * 32;
    const int tx = threadIdx.x & 31, ty = threadIdx.x >> 5;  // 32 x 8
#pragma unroll
    for (int i = 0; i < 4; i++)
        t[ty + 8 * i][tx] = W[(size_t)(k0 + ty + 8 * i) * DMODEL + n0 + tx];
    __syncthreads();
#pragma unroll
    for (int i = 0; i < 4; i++) {
        int n = n0 + ty + 8 * i;
        float x = t[tx][ty + 8 * i];
        unsigned short b0, b1, b2;
        split3(x, b0, b1, b2);
        size_t o = (size_t)n * DMODEL + k0 + tx;
        h0[o] = b0; h1[o] = b1; h2[o] = b2;
    }
}

// ---------------------------------------------------------------------------
// K1: QKV GEMM on TENSOR CORES via bf16 3-split (6 cross-products).
// x = x0+x1+x2 (bf16 each, ~24 mantissa bits). Products kept: (0,0),(0,1),
// (1,0),(0,2),(1,1),(2,0); dropped terms are ~2^-26 relative each ->
// accumulated error ~5e-7 relative, same grade as the fp32 FFMA chain.
//
// Tiles: 128 rows x 64 cols per CTA, k-step 32; grid (48,32): blockIdx.x
// selects {which, ncol}. Fragment layout = R11-proven word permute
// w' = (w&3)*4 + (w>>2) at row pitch 16 words -> each (row, split) frag set
// is one uint4 LDS, conflict-free. Double-buffered smem (72KB), LDG prefetch
// -> compute -> STS -> one barrier per k-step.
// ---------------------------------------------------------------------------
#define GM_BUF_WORDS 9216   // A: 3*2048, B at +6144: 3*1024
#define GM_SMEM_BYTES (2 * GM_BUF_WORDS * 4)

__global__ __launch_bounds__(256, 2) void sgemm_qkv_tc(
    const unsigned short* __restrict__ xs0, const unsigned short* __restrict__ xs1,
    const unsigned short* __restrict__ xs2,
    const unsigned short* __restrict__ ws0, const unsigned short* __restrict__ ws1,
    const unsigned short* __restrict__ ws2,
    const float* __restrict__ bq, const float* __restrict__ bk,
    const float* __restrict__ bv,
    float* __restrict__ Cq, float* __restrict__ Ck, float* __restrict__ Cv)
{
    extern __shared__ unsigned smu[];

    const int tid = threadIdx.x;
    const int w = tid >> 5, lane = tid & 31;
    const int g = lane >> 2, t4 = lane & 3;
    const int which = blockIdx.x >> 4;
    const int ncol = (blockIdx.x & 15) * 64;
    const int by = blockIdx.y * 128;

    const float* bias = (which == 0) ? bq : (which == 1) ? bk : bv;
    float* C = (which == 0) ? Cq : (which == 1) ? Ck : Cv;

    const unsigned* xp[3] = {(const unsigned*)xs0, (const unsigned*)xs1,
                             (const unsigned*)xs2};
    const size_t woff = (size_t)which * (DMODEL * DMODEL / 2);
    const unsigned* wp[3] = {(const unsigned*)ws0 + woff,
                             (const unsigned*)ws1 + woff,
                             (const unsigned*)ws2 + woff};

    const int ar = tid >> 1, ah = tid & 1;   // A fill: row, 8-word half
    const int brn = tid >> 2, bt = tid & 3;  // B fill: row, 4-word quarter

    float cacc[8][4];
#pragma unroll
    for (int nt = 0; nt < 8; nt++)
#pragma unroll
        for (int e = 0; e < 4; e++) cacc[nt][e] = 0.f;

    // ---- prologue: fill buf 0 (k-step 0)
    {
#pragma unroll
        for (int s3 = 0; s3 < 3; s3++) {
            const unsigned* src = &xp[s3][(size_t)(by + ar) * 512 + ah * 8];
            uint4 u0 = *(const uint4*)src;
            uint4 u1 = *(const uint4*)(src + 4);
            unsigned* dst = &smu[s3 * 2048 + ar * 16];
            unsigned vals[8] = {u0.x, u0.y, u0.z, u0.w, u1.x, u1.y, u1.z, u1.w};
#pragma unroll
            for (int c = 0; c < 8; c++) {
                int wd = ah * 8 + c;
                dst[(wd & 3) * 4 + (wd >> 2)] = vals[c];
            }
        }
#pragma unroll
        for (int s3 = 0; s3 < 3; s3++) {
            uint4 u = *(const uint4*)&wp[s3][(size_t)(ncol + brn) * 512 + bt * 4];
            unsigned* dst = &smu[6144 + s3 * 1024 + brn * 16];
            unsigned vals[4] = {u.x, u.y, u.z, u.w};
#pragma unroll
            for (int c = 0; c < 4; c++) {
                int wd = bt * 4 + c;
                dst[(wd & 3) * 4 + (wd >> 2)] = vals[c];
            }
        }
    }
    __syncthreads();

    for (int ks = 0; ks < 32; ks++) {
        const int cur = ks & 1;
        const unsigned* Ab = &smu[cur * GM_BUF_WORDS];
        const unsigned* Bb = Ab + 6144;

        // prefetch next k-step from global
        uint4 pa[3][2], pb[3];
        const bool more = (ks + 1) < 32;
        if (more) {
            const int kw = (ks + 1) * 16;
#pragma unroll
            for (int s3 = 0; s3 < 3; s3++) {
                const unsigned* src = &xp[s3][(size_t)(by + ar) * 512 + kw + ah * 8];
                pa[s3][0] = *(const uint4*)src;
                pa[s3][1] = *(const uint4*)(src + 4);
                pb[s3] = *(const uint4*)&wp[s3][(size_t)(ncol + brn) * 512 + kw + bt * 4];
            }
        }

        // A fragments: per split, rows g and g+8; uint4 covers both k-slices
        uint4 alo[3], ahi[3];
#pragma unroll
        for (int s3 = 0; s3 < 3; s3++) {
            alo[s3] = *(const uint4*)&Ab[s3 * 2048 + (w * 16 + g) * 16 + t4 * 4];
            ahi[s3] = *(const uint4*)&Ab[s3 * 2048 + (w * 16 + g + 8) * 16 + t4 * 4];
        }

#pragma unroll
        for (int nt = 0; nt < 8; nt++) {
            uint4 b0 = *(const uint4*)&Bb[0 * 1024 + (nt * 8 + g) * 16 + t4 * 4];
            uint4 b1 = *(const uint4*)&Bb[1 * 1024 + (nt * 8 + g) * 16 + t4 * 4];
            uint4 b2 = *(const uint4*)&Bb[2 * 1024 + (nt * 8 + g) * 16 + t4 * 4];
            float& c0 = cacc[nt][0];
            float& c1 = cacc[nt][1];
            float& c2 = cacc[nt][2];
            float& c3 = cacc[nt][3];
            // slice 0: A frags {alo.x, ahi.x, alo.y, ahi.y}, B (b.x, b.y)
            mma_bf16(c0, c1, c2, c3, alo[0].x, ahi[0].x, alo[0].y, ahi[0].y, b0.x, b0.y);
            mma_bf16(c0, c1, c2, c3, alo[0].x, ahi[0].x, alo[0].y, ahi[0].y, b1.x, b1.y);
            mma_bf16(c0, c1, c2, c3, alo[1].x, ahi[1].x, alo[1].y, ahi[1].y, b0.x, b0.y);
            mma_bf16(c0, c1, c2, c3, alo[0].x, ahi[0].x, alo[0].y, ahi[0].y, b2.x, b2.y);
            mma_bf16(c0, c1, c2, c3, alo[1].x, ahi[1].x, alo[1].y, ahi[1].y, b1.x, b1.y);
            mma_bf16(c0, c1, c2, c3, alo[2].x, ahi[2].x, alo[2].y, ahi[2].y, b0.x, b0.y);
            // slice 1: A frags {alo.z, ahi.z, alo.w, ahi.w}, B (b.z, b.w)
            mma_bf16(c0, c1, c2, c3, alo[0].z, ahi[0].z, alo[0].w, ahi[0].w, b0.z, b0.w);
            mma_bf16(c0, c1, c2, c3, alo[0].z, ahi[0].z, alo[0].w, ahi[0].w, b1.z, b1.w);
            mma_bf16(c0, c1, c2, c3, alo[1].z, ahi[1].z, alo[1].w, ahi[1].w, b0.z, b0.w);
            mma_bf16(c0, c1, c2, c3, alo[0].z, ahi[0].z, alo[0].w, ahi[0].w, b2.z, b2.w);
            mma_bf16(c0, c1, c2, c3, alo[1].z, ahi[1].z, alo[1].w, ahi[1].w, b1.z, b1.w);
            mma_bf16(c0, c1, c2, c3, alo[2].z, ahi[2].z, alo[2].w, ahi[2].w, b0.z, b0.w);
        }

        // store prefetched data into the other buffer
        if (more) {
            unsigned* nb = &smu[(cur ^ 1) * GM_BUF_WORDS];
#pragma unroll
            for (int s3 = 0; s3 < 3; s3++) {
                unsigned* dst = &nb[s3 * 2048 + ar * 16];
                unsigned vals[8] = {pa[s3][0].x, pa[s3][0].y, pa[s3][0].z, pa[s3][0].w,
                                    pa[s3][1].x, pa[s3][1].y, pa[s3][1].z, pa[s3][1].w};
#pragma unroll
                for (int c = 0; c < 8; c++) {
                    int wd = ah * 8 + c;
                    dst[(wd & 3) * 4 + (wd >> 2)] = vals[c];
                }
                unsigned* dstb = &nb[6144 + s3 * 1024 + brn * 16];
                unsigned valsb[4] = {pb[s3].x, pb[s3].y, pb[s3].z, pb[s3].w};
#pragma unroll
                for (int c = 0; c < 4; c++) {
                    int wd = bt * 4 + c;
                    dstb[(wd & 3) * 4 + (wd >> 2)] = valsb[c];
                }
            }
        }
        __syncthreads();
    }

    // epilogue
    const int row0 = by + w * 16 + g;
    const int row1 = row0 + 8;
#pragma unroll
    for (int nt = 0; nt < 8; nt++) {
        int col = ncol + nt * 8 + 2 * t4;
        float2 bb = *(const float2*)&bias[col];
        float2 o0 = {cacc[nt][0] + bb.x, cacc[nt][1] + bb.y};
        float2 o1 = {cacc[nt][2] + bb.x, cacc[nt][3] + bb.y};
        *(float2*)&C[(size_t)row0 * DMODEL + col] = o0;
        *(float2*)&C[(size_t)row1 * DMODEL + col] = o1;
    }
}

// ---------------------------------------------------------------------------
// K2: attention = bf16 TENSOR-CORE FILTER + EXACT FP32 RESCUE (R11-verbatim)
// ---------------------------------------------------------------------------
#define MARGIN 0.5f
#define KPITCH_W 36
#define ATT_SMEM_BYTES (128 * 68 * 4)

__global__ __launch_bounds__(256, 2) void attn_kernel()
{
    extern __shared__ float smf[];
    unsigned* ksw = (unsigned*)smf;

    const int tid = threadIdx.x;
    const int w = tid >> 5, lane = tid & 31;
    const int g = lane >> 2, t4 = lane & 3;
    const int q0 = blockIdx.x * 128;
    const int hb = blockIdx.y * DH;
    const int R0 = q0 + w * 16 + g;
    const int R1 = R0 + 8;
    const unsigned qmask = 0xFu << (lane & 28);

    for (int it = 0; it < 8; it++) {
        int idx = tid + it * 256;
        int r = idx >> 4, d = (idx & 15) * 4;
        float4 t = *(const float4*)&g_q[(size_t)(q0 + r) * DMODEL + hb + d];
        *(float4*)&smf[r * 68 + d] = t;
    }
    __syncthreads();
    unsigned afr[4][4];
    {
        const float* q0p = &smf[(w * 16 + g) * 68];
        const float* q1p = q0p + 8 * 68;
#pragma unroll
        for (int s = 0; s < 4; s++) {
            int kb = 16 * s + 2 * t4;
            afr[s][0] = bf2(q0p[kb], q0p[kb + 1]);
            afr[s][1] = bf2(q1p[kb], q1p[kb + 1]);
            afr[s][2] = bf2(q0p[kb + 8], q0p[kb + 9]);
            afr[s][3] = bf2(q1p[kb + 8], q1p[kb + 9]);
        }
    }

    float run0 = INFINITY, run1 = INFINITY;
    float rmax0 = -INFINITY, rmax1 = -INFINITY;
    float rsum0 = 0.f, rsum1 = 0.f;
    float acc0[16], acc1[16];
#pragma unroll
    for (int d = 0; d < 16; d++) { acc0[d] = 0.f; acc1[d] = 0.f; }

    const int A0 = q0 + w * 16;
    for (int k0 = 0; k0 < SQ; k0 += 128) {
        __syncthreads();
        for (int it = 0; it < 8; it++) {
            int idx = tid + it * 256;
            int r = idx >> 4, d = (idx & 15) * 4;
            float4 t = *(const float4*)&g_k[(size_t)(k0 + r) * DMODEL + hb + d];
            int w0 = d >> 1, w1 = w0 + 1;
            ksw[r * KPITCH_W + ((w0 & 3) * 8 + (w0 >> 2))] = bf2(t.x, t.y);
            ksw[r * KPITCH_W + ((w1 & 3) * 8 + (w1 >> 2))] = bf2(t.z, t.w);
        }
        __syncthreads();

        const bool careful = (k0 <= A0 + 15) && (k0 + 127 >= A0 - 1);

#pragma unroll 1
        for (int t = 0; t < 16; t++) {
            const uint4* kf = (const uint4*)&ksw[(t * 8 + g) * KPITCH_W + t4 * 8];
            uint4 u0 = kf[0];
            uint4 u1 = kf[1];
            float c0 = 0.f, c1 = 0.f, c2 = 0.f, c3 = 0.f;
            mma_bf16(c0, c1, c2, c3,
                     afr[0][0], afr[0][1], afr[0][2], afr[0][3], u0.x, u0.y);
            mma_bf16(c0, c1, c2, c3,
                     afr[1][0], afr[1][1], afr[1][2], afr[1][3], u0.z, u0.w);
            mma_bf16(c0, c1, c2, c3,
                     afr[2][0], afr[2][1], afr[2][2], afr[2][3], u1.x, u1.y);
            mma_bf16(c0, c1, c2, c3,
                     afr[3][0], afr[3][1], afr[3][2], afr[3][3], u1.z, u1.w);

            const int j0 = k0 + 8 * t + 2 * t4;
            if (careful) {
                if (j0 == R0 || j0 == R0 - 1) c0 = INFINITY;
                if (j0 + 1 == R0 || j0 + 1 == R0 - 1) c1 = INFINITY;
                if (j0 == R1 || j0 == R1 - 1) c2 = INFINITY;
                if (j0 + 1 == R1 || j0 + 1 == R1 - 1) c3 = INFINITY;
            }
            float m0 = fminf(c0, c1), m1 = fminf(c2, c3);
            run0 = fminf(run0, m0);
            run1 = fminf(run1, m1);
            bool fl = (m0 <= run0 + MARGIN) || (m1 <= run1 + MARGIN);

            if (__any_sync(0xffffffffu, fl)) {
                unsigned bal[4];
                bal[0] = __ballot_sync(0xffffffffu, c0 <= run0 + MARGIN);
                bal[1] = __ballot_sync(0xffffffffu, c1 <= run0 + MARGIN);
                bal[2] = __ballot_sync(0xffffffffu, c2 <= run1 + MARGIN);
                bal[3] = __ballot_sync(0xffffffffu, c3 <= run1 + MARGIN);
#pragma unroll
                for (int e = 0; e < 4; e++) {
                    unsigned qb = (bal[e] >> (lane & 28)) & 0xFu;
                    const int i = (e >= 2) ? R1 : R0;
                    while (qb) {
                        int b = __ffs((int)qb) - 1;
                        qb &= qb - 1;
                        int j = k0 + 8 * t + 2 * b + (e & 1);
                        const float* qg = &g_q[(size_t)i * DMODEL + hb + t4 * 16];
                        const float* kg = &g_k[(size_t)j * DMODEL + hb + t4 * 16];
                        float s = 0.f;
#pragma unroll
                        for (int c4 = 0; c4 < 4; c4++) {
                            float4 qv = *(const float4*)&qg[c4 * 4];
                            float4 kv = *(const float4*)&kg[c4 * 4];
                            s = fmaf(qv.x, kv.x, s);
                            s = fmaf(qv.y, kv.y, s);
                            s = fmaf(qv.z, kv.z, s);
                            s = fmaf(qv.w, kv.w, s);
                        }
                        s += __shfl_xor_sync(qmask, s, 1);
                        s += __shfl_xor_sync(qmask, s, 2);
                        float y = s * 0.125f;
                        if (!(j == i || j == i - 1)) y = y * -1000000000.0f;
                        const float* vg = &g_v[(size_t)j * DMODEL + hb + t4 * 16];
                        if (e < 2) {
                            if (y > rmax0) {
                                float scl = expf(rmax0 - y);
                                rsum0 *= scl;
#pragma unroll
                                for (int d = 0; d < 16; d++) acc0[d] *= scl;
                                rmax0 = y;
                            }
                            float p = expf(y - rmax0);
                            rsum0 += p;
#pragma unroll
                            for (int c4 = 0; c4 < 4; c4++) {
                                float4 vv = *(const float4*)&vg[c4 * 4];
                                acc0[c4 * 4 + 0] = fmaf(p, vv.x, acc0[c4 * 4 + 0]);
                                acc0[c4 * 4 + 1] = fmaf(p, vv.y, acc0[c4 * 4 + 1]);
                                acc0[c4 * 4 + 2] = fmaf(p, vv.z, acc0[c4 * 4 + 2]);
                                acc0[c4 * 4 + 3] = fmaf(p, vv.w, acc0[c4 * 4 + 3]);
                            }
                        } else {
                            if (y > rmax1) {
                                float scl = expf(rmax1 - y);
                                rsum1 *= scl;
#pragma unroll
                                for (int d = 0; d < 16; d++) acc1[d] *= scl;
                                rmax1 = y;
                            }
                            float p = expf(y - rmax1);
                            rsum1 += p;
#pragma unroll
                            for (int c4 = 0; c4 < 4; c4++) {
                                float4 vv = *(const float4*)&vg[c4 * 4];
                                acc1[c4 * 4 + 0] = fmaf(p, vv.x, acc1[c4 * 4 + 0]);
                                acc1[c4 * 4 + 1] = fmaf(p, vv.y, acc1[c4 * 4 + 1]);
                                acc1[c4 * 4 + 2] = fmaf(p, vv.z, acc1[c4 * 4 + 2]);
                                acc1[c4 * 4 + 3] = fmaf(p, vv.w, acc1[c4 * 4 + 3]);
                            }
                        }
                    }
                }
            }
        }
        run0 = fminf(run0, __shfl_xor_sync(0xffffffffu, run0, 1));
        run0 = fminf(run0, __shfl_xor_sync(0xffffffffu, run0, 2));
        run1 = fminf(run1, __shfl_xor_sync(0xffffffffu, run1, 1));
        run1 = fminf(run1, __shfl_xor_sync(0xffffffffu, run1, 2));
    }

    {
        float inv0 = 1.f / rsum0;
        float inv1 = 1.f / rsum1;
        float* o0 = &g_attn[(size_t)R0 * DMODEL + hb + t4 * 16];
        float* o1 = &g_attn[(size_t)R1 * DMODEL + hb + t4 * 16];
#pragma unroll
        for (int c4 = 0; c4 < 4; c4++) {
            float4 a = {acc0[c4 * 4 + 0] * inv0, acc0[c4 * 4 + 1] * inv0,
                        acc0[c4 * 4 + 2] * inv0, acc0[c4 * 4 + 3] * inv0};
            float4 b = {acc1[c4 * 4 + 0] * inv1, acc1[c4 * 4 + 1] * inv1,
                        acc1[c4 * 4 + 2] * inv1, acc1[c4 * 4 + 3] * inv1};
            *(float4*)&o0[c4 * 4] = a;
            *(float4*)&o1[c4 * 4] = b;
        }
    }
}

// ---------------------------------------------------------------------------
// K3: out[4096,64] = g_attn[4096,1024] @ Wm[1024,64] + bm  (verbatim)
// ---------------------------------------------------------------------------
__global__ __launch_bounds__(256) void sgemm_out(
    const float* __restrict__ A, const float* __restrict__ B,
    const float* __restrict__ bias, float* __restrict__ C)
{
    __shared__ float As[16][64];
    __shared__ float Bs[16][64];

    const int tid = threadIdx.x;
    const int tx = tid & 15, ty = tid >> 4;
    const int by = blockIdx.x * 64;

    const int ar = tid >> 2;
    const int ac = (tid & 3) * 4;
    const int br = tid >> 4;
    const int bc = (tid & 15) * 4;

    float acc[4][4];
#pragma unroll
    for (int i = 0; i < 4; i++)
#pragma unroll
        for (int j = 0; j < 4; j++) acc[i][j] = 0.f;

    for (int k0 = 0; k0 < DMODEL; k0 += 16) {
        float4 av = *(const float4*)&A[(size_t)(by + ar) * DMODEL + k0 + ac];
        float4 bv = *(const float4*)&B[(size_t)(k0 + br) * 64 + bc];
        As[ac + 0][ar] = av.x;
        As[ac + 1][ar] = av.y;
        As[ac + 2][ar] = av.z;
        As[ac + 3][ar] = av.w;
        *(float4*)&Bs[br][bc] = bv;
        __syncthreads();
#pragma unroll
        for (int kk = 0; kk < 16; kk++) {
            float4 a = *(const float4*)&As[kk][ty * 4];
            float4 b = *(const float4*)&Bs[kk][tx * 4];
            float av4[4] = {a.x, a.y, a.z, a.w};
            float bv4[4] = {b.x, b.y, b.z, b.w};
#pragma unroll
            for (int i = 0; i < 4; i++)
#pragma unroll
                for (int j = 0; j < 4; j++)
                    acc[i][j] = fmaf(av4[i], bv4[j], acc[i][j]);
        }
        __syncthreads();
    }

#pragma unroll
    for (int i = 0; i < 4; i++) {
        int row = by + ty * 4 + i;
        float4 o;
        o.x = acc[i][0] + bias[tx * 4 + 0];
        o.y = acc[i][1] + bias[tx * 4 + 1];
        o.z = acc[i][2] + bias[tx * 4 + 2];
        o.w = acc[i][3] + bias[tx * 4 + 3];
        *(float4*)&C[(size_t)row * 64 + tx * 4] = o;
    }
}

// ---------------------------------------------------------------------------
// kernel_launch
// ---------------------------------------------------------------------------
extern "C" void kernel_launch(void* const* d_in, const int* in_sizes, int n_in,
                              void* d_out, int out_size)
{
    const float* X  = (const float*)d_in[0];
    const float* Wq = (const float*)d_in[2];
    const float* bq = (const float*)d_in[3];
    const float* Wk = (const float*)d_in[4];
    const float* bk = (const float*)d_in[5];
    const float* Wv = (const float*)d_in[6];
    const float* bv = (const float*)d_in[7];
    const float* Wm = (const float*)d_in[8];
    const float* bm = (const float*)d_in[9];
    float* out = (float*)d_out;

    float *qp, *kp, *vp, *ap;
    cudaGetSymbolAddress((void**)&qp, g_q);
    cudaGetSymbolAddress((void**)&kp, g_k);
    cudaGetSymbolAddress((void**)&vp, g_v);
    cudaGetSymbolAddress((void**)&ap, g_attn);
    unsigned short *x0, *x1, *x2, *w0, *w1, *w2;
    cudaGetSymbolAddress((void**)&x0, g_xs0);
    cudaGetSymbolAddress((void**)&x1, g_xs1);
    cudaGetSymbolAddress((void**)&x2, g_xs2);
    cudaGetSymbolAddress((void**)&w0, g_ws0);
    cudaGetSymbolAddress((void**)&w1, g_ws1);
    cudaGetSymbolAddress((void**)&w2, g_ws2);

    const int WSZ = DMODEL * DMODEL;
    prep_x<<<4096, 256>>>(X, x0, x1, x2, SQ * DMODEL);
    prep_wt<<<dim3(32, 32), 256>>>(Wq, w0, w1, w2);
    prep_wt<<<dim3(32, 32), 256>>>(Wk, w0 + WSZ, w1 + WSZ, w2 + WSZ);
    prep_wt<<<dim3(32, 32), 256>>>(Wv, w0 + 2 * WSZ, w1 + 2 * WSZ, w2 + 2 * WSZ);

    cudaFuncSetAttribute(sgemm_qkv_tc,
                         cudaFuncAttributeMaxDynamicSharedMemorySize,
                         GM_SMEM_BYTES);
    sgemm_qkv_tc<<<dim3(48, 32), 256, GM_SMEM_BYTES>>>(
        x0, x1, x2, w0, w1, w2, bq, bk, bv, qp, kp, vp);

    cudaFuncSetAttribute(attn_kernel,
                         cudaFuncAttributeMaxDynamicSharedMemorySize,
                         ATT_SMEM_BYTES);
    attn_kernel<<<dim3(SQ / 128, NH), 256, ATT_SMEM_BYTES>>>();

    sgemm_out<<<SQ / 64, 256>>>(ap, Wm, bm, out);
}

// round 14
// speedup vs baseline: 1.4168x; 1.4168x over previous
#include <cuda_runtime.h>
#include <math.h>

#define SQ 4096
#define DMODEL 1024
#define NH 16
#define DH 64

typedef unsigned long long ull;

// Scratch (allocation-free rule: __device__ globals)
__device__ float g_q[SQ * DMODEL];
__device__ float g_k[SQ * DMODEL];
__device__ float g_v[SQ * DMODEL];
__device__ float g_attn[SQ * DMODEL];

// ---------------------------------------------------------------------------
// Packed fp32x2 helpers ("l" = b64 integer carrier)
// ---------------------------------------------------------------------------
__device__ __forceinline__ ull ffma2(ull a, ull b, ull c) {
    ull r;
    asm("fma.rn.f32x2 %0, %1, %2, %3;" : "=l"(r) : "l"(a), "l"(b), "l"(c));
    return r;
}
__device__ __forceinline__ ull pack2(float x) {
    ull r;
    asm("mov.b64 %0, {%1, %1};" : "=l"(r) : "f"(x));
    return r;
}
__device__ __forceinline__ void unpack2(ull d, float& lo, float& hi) {
    asm("mov.b64 {%0, %1}, %2;" : "=f"(lo), "=f"(hi) : "l"(d));
}

// bf16 helpers for the attention filter
// pack {lo -> bits[15:0], hi -> bits[31:16]}
__device__ __forceinline__ unsigned bf2(float lo, float hi) {
    unsigned r;
    asm("cvt.rn.bf16x2.f32 %0, %1, %2;" : "=r"(r) : "f"(hi), "f"(lo));
    return r;
}
__device__ __forceinline__ void mma_bf16(
    float& c0, float& c1, float& c2, float& c3,
    unsigned a0, unsigned a1, unsigned a2, unsigned a3,
    unsigned b0, unsigned b1)
{
    asm volatile(
        "mma.sync.aligned.m16n8k16.row.col.f32.bf16.bf16.f32 "
        "{%0,%1,%2,%3}, {%4,%5,%6,%7}, {%8,%9}, {%0,%1,%2,%3};"
        : "+f"(c0), "+f"(c1), "+f"(c2), "+f"(c3)
        : "r"(a0), "r"(a1), "r"(a2), "r"(a3), "r"(b0), "r"(b1));
}

// ---------------------------------------------------------------------------
// K1: FUSED QKV SGEMM (R8/R11-proven FFMA2 path, ~574us).
// Measured legacy-MMA throughput (R13: 174 TF/s effective) proves the 6x
// FLOP-inflated bf16-split tensor GEMM cannot beat this on sm_100a's
// compatibility MMA path — reverted to FFMA2.
// ---------------------------------------------------------------------------
__global__ __launch_bounds__(256, 2) void sgemm_qkv(
    const float* __restrict__ A,
    const float* __restrict__ Wq, const float* __restrict__ Wk,
    const float* __restrict__ Wv,
    const float* __restrict__ bq, const float* __restrict__ bk,
    const float* __restrict__ bv,
    float* __restrict__ Cq, float* __restrict__ Ck, float* __restrict__ Cv)
{
    const int which = blockIdx.x >> 3;
    const float* __restrict__ B = (which == 0) ? Wq : (which == 1) ? Wk : Wv;
    const float* __restrict__ bias = (which == 0) ? bq : (which == 1) ? bk : bv;
    float* __restrict__ C = (which == 0) ? Cq : (which == 1) ? Ck : Cv;

    __shared__ float As[8][128];
    __shared__ float Bs[8][128];

    const int tid = threadIdx.x;
    const int tx = tid & 15, ty = tid >> 4;
    const int bx = (blockIdx.x & 7) * 128, by = blockIdx.y * 128;

    const int ar = tid >> 1;
    const int ac = (tid & 1) * 4;
    const int br = tid >> 5;
    const int bc = (tid & 31) * 4;

    ull acc2[8][4];
#pragma unroll
    for (int i = 0; i < 8; i++)
#pragma unroll
        for (int j = 0; j < 4; j++) acc2[i][j] = pack2(0.f);

    const float* Aptr = A + (size_t)(by + ar) * DMODEL + ac;
    const float* Bptr = B + (size_t)br * DMODEL + bx + bc;

    float4 av = *(const float4*)(Aptr);
    float4 bv4 = *(const float4*)(Bptr);

    for (int k0 = 0; k0 < DMODEL; k0 += 8) {
        As[ac + 0][ar] = av.x;
        As[ac + 1][ar] = av.y;
        As[ac + 2][ar] = av.z;
        As[ac + 3][ar] = av.w;
        *(float4*)&Bs[br][bc] = bv4;
        __syncthreads();

        if (k0 + 8 < DMODEL) {
            av = *(const float4*)(Aptr + k0 + 8);
            bv4 = *(const float4*)(Bptr + (size_t)(k0 + 8) * DMODEL);
        }

#pragma unroll
        for (int kk = 0; kk < 8; kk++) {
            ulonglong2 bA = *(const ulonglong2*)&Bs[kk][4 * tx];
            ulonglong2 bB = *(const ulonglong2*)&Bs[kk][64 + 4 * tx];
            float4 a0 = *(const float4*)&As[kk][ty * 8];
            float4 a1 = *(const float4*)&As[kk][ty * 8 + 4];
            float aa[8] = {a0.x, a0.y, a0.z, a0.w, a1.x, a1.y, a1.z, a1.w};
#pragma unroll
            for (int i = 0; i < 8; i++) {
                ull a2 = pack2(aa[i]);
                acc2[i][0] = ffma2(a2, bA.x, acc2[i][0]);
                acc2[i][1] = ffma2(a2, bA.y, acc2[i][1]);
                acc2[i][2] = ffma2(a2, bB.x, acc2[i][2]);
                acc2[i][3] = ffma2(a2, bB.y, acc2[i][3]);
            }
        }
        __syncthreads();
    }

    const int colA = bx + 4 * tx;
    const int colB = colA + 64;
    float4 biasA = *(const float4*)&bias[colA];
    float4 biasB = *(const float4*)&bias[colB];
#pragma unroll
    for (int i = 0; i < 8; i++) {
        int row = by + ty * 8 + i;
        float x0, x1, x2, x3;
        unpack2(acc2[i][0], x0, x1);
        unpack2(acc2[i][1], x2, x3);
        float4 oA = {x0 + biasA.x, x1 + biasA.y, x2 + biasA.z, x3 + biasA.w};
        unpack2(acc2[i][2], x0, x1);
        unpack2(acc2[i][3], x2, x3);
        float4 oB = {x0 + biasB.x, x1 + biasB.y, x2 + biasB.z, x3 + biasB.w};
        *(float4*)&C[(size_t)row * DMODEL + colA] = oA;
        *(float4*)&C[(size_t)row * DMODEL + colB] = oB;
    }
}

// ---------------------------------------------------------------------------
// K2: attention = bf16 TENSOR-CORE FILTER + EXACT FP32 RESCUE (R11 math)
// with PAIR-MERGED GATING: two 8-key sub-tiles (8 MMAs) share one
// min/run-update/__any_sync block, halving common-path gating overhead.
// Safe by monotonicity: run-min >= final-min under ANY update schedule, so
// the candidate superset property (every entry with nonzero exact fp32 exp
// is rescued) is preserved; rescued entries are recomputed exactly in fp32.
// ---------------------------------------------------------------------------
#define MARGIN 0.5f
#define KPITCH_W 36
#define ATT_SMEM_BYTES (128 * 68 * 4)   // Q staging (34816B) > K tile (18432B)

__global__ __launch_bounds__(256, 2) void attn_kernel()
{
    extern __shared__ float smf[];
    unsigned* ksw = (unsigned*)smf;

    const int tid = threadIdx.x;
    const int w = tid >> 5, lane = tid & 31;
    const int g = lane >> 2, t4 = lane & 3;
    const int q0 = blockIdx.x * 128;
    const int hb = blockIdx.y * DH;
    const int R0 = q0 + w * 16 + g;
    const int R1 = R0 + 8;
    const unsigned qmask = 0xFu << (lane & 28);

    // ---- Phase 1: stage Q (fp32) and extract bf16 A-fragments
    for (int it = 0; it < 8; it++) {
        int idx = tid + it * 256;
        int r = idx >> 4, d = (idx & 15) * 4;
        float4 t = *(const float4*)&g_q[(size_t)(q0 + r) * DMODEL + hb + d];
        *(float4*)&smf[r * 68 + d] = t;
    }
    __syncthreads();
    unsigned afr[4][4];
    {
        const float* q0p = &smf[(w * 16 + g) * 68];
        const float* q1p = q0p + 8 * 68;
#pragma unroll
        for (int s = 0; s < 4; s++) {
            int kb = 16 * s + 2 * t4;
            afr[s][0] = bf2(q0p[kb], q0p[kb + 1]);
            afr[s][1] = bf2(q1p[kb], q1p[kb + 1]);
            afr[s][2] = bf2(q0p[kb + 8], q0p[kb + 9]);
            afr[s][3] = bf2(q1p[kb + 8], q1p[kb + 9]);
        }
    }

    float run0 = INFINITY, run1 = INFINITY;       // approx s-min (gating only)
    float rmax0 = -INFINITY, rmax1 = -INFINITY;   // exact-side state
    float rsum0 = 0.f, rsum1 = 0.f;
    float acc0[16], acc1[16];
#pragma unroll
    for (int d = 0; d < 16; d++) { acc0[d] = 0.f; acc1[d] = 0.f; }

    const int A0 = q0 + w * 16;
    for (int k0 = 0; k0 < SQ; k0 += 128) {
        __syncthreads();  // previous tile's readers done (1st iter: afr done)
        // fill K tile: bf16x2, word-permuted
        for (int it = 0; it < 8; it++) {
            int idx = tid + it * 256;
            int r = idx >> 4, d = (idx & 15) * 4;
            float4 t = *(const float4*)&g_k[(size_t)(k0 + r) * DMODEL + hb + d];
            int w0 = d >> 1, w1 = w0 + 1;
            ksw[r * KPITCH_W + ((w0 & 3) * 8 + (w0 >> 2))] = bf2(t.x, t.y);
            ksw[r * KPITCH_W + ((w1 & 3) * 8 + (w1 >> 2))] = bf2(t.z, t.w);
        }
        __syncthreads();

        const bool careful = (k0 <= A0 + 15) && (k0 + 127 >= A0 - 1);

#pragma unroll 1
        for (int tp = 0; tp < 8; tp++) {
            const int tA = 2 * tp, tB = 2 * tp + 1;
            // ---- sub-tile A (keys k0+8*tA .. +7)
            const uint4* kfA = (const uint4*)&ksw[(tA * 8 + g) * KPITCH_W + t4 * 8];
            uint4 uA0 = kfA[0];
            uint4 uA1 = kfA[1];
            float a0 = 0.f, a1 = 0.f, a2 = 0.f, a3 = 0.f;
            mma_bf16(a0, a1, a2, a3,
                     afr[0][0], afr[0][1], afr[0][2], afr[0][3], uA0.x, uA0.y);
            mma_bf16(a0, a1, a2, a3,
                     afr[1][0], afr[1][1], afr[1][2], afr[1][3], uA0.z, uA0.w);
            mma_bf16(a0, a1, a2, a3,
                     afr[2][0], afr[2][1], afr[2][2], afr[2][3], uA1.x, uA1.y);
            mma_bf16(a0, a1, a2, a3,
                     afr[3][0], afr[3][1], afr[3][2], afr[3][3], uA1.z, uA1.w);
            // ---- sub-tile B (keys k0+8*tB .. +7)
            const uint4* kfB = (const uint4*)&ksw[(tB * 8 + g) * KPITCH_W + t4 * 8];
            uint4 uB0 = kfB[0];
            uint4 uB1 = kfB[1];
            float b0 = 0.f, b1 = 0.f, b2 = 0.f, b3 = 0.f;
            mma_bf16(b0, b1, b2, b3,
                     afr[0][0], afr[0][1], afr[0][2], afr[0][3], uB0.x, uB0.y);
            mma_bf16(b0, b1, b2, b3,
                     afr[1][0], afr[1][1], afr[1][2], afr[1][3], uB0.z, uB0.w);
            mma_bf16(b0, b1, b2, b3,
                     afr[2][0], afr[2][1], afr[2][2], afr[2][3], uB1.x, uB1.y);
            mma_bf16(b0, b1, b2, b3,
                     afr[3][0], afr[3][1], afr[3][2], afr[3][3], uB1.z, uB1.w);

            const int jA = k0 + 8 * tA + 2 * t4;
            const int jB = k0 + 8 * tB + 2 * t4;
            if (careful) {
                // exclude band cols from the filter min/candidates
                if (jA == R0 || jA == R0 - 1) a0 = INFINITY;
                if (jA + 1 == R0 || jA + 1 == R0 - 1) a1 = INFINITY;
                if (jA == R1 || jA == R1 - 1) a2 = INFINITY;
                if (jA + 1 == R1 || jA + 1 == R1 - 1) a3 = INFINITY;
                if (jB == R0 || jB == R0 - 1) b0 = INFINITY;
                if (jB + 1 == R0 || jB + 1 == R0 - 1) b1 = INFINITY;
                if (jB == R1 || jB == R1 - 1) b2 = INFINITY;
                if (jB + 1 == R1 || jB + 1 == R1 - 1) b3 = INFINITY;
            }
            // merged pair min + single run update + single warp vote
            float m0 = fminf(fminf(a0, a1), fminf(b0, b1));
            float m1 = fminf(fminf(a2, a3), fminf(b2, b3));
            run0 = fminf(run0, m0);
            run1 = fminf(run1, m1);
            bool fl = (m0 <= run0 + MARGIN) || (m1 <= run1 + MARGIN);

            if (__any_sync(0xffffffffu, fl)) {
                const float th0 = run0 + MARGIN;
                const float th1 = run1 + MARGIN;
                unsigned bal[8];
                bal[0] = __ballot_sync(0xffffffffu, a0 <= th0);
                bal[1] = __ballot_sync(0xffffffffu, a1 <= th0);
                bal[2] = __ballot_sync(0xffffffffu, a2 <= th1);
                bal[3] = __ballot_sync(0xffffffffu, a3 <= th1);
                bal[4] = __ballot_sync(0xffffffffu, b0 <= th0);
                bal[5] = __ballot_sync(0xffffffffu, b1 <= th0);
                bal[6] = __ballot_sync(0xffffffffu, b2 <= th1);
                bal[7] = __ballot_sync(0xffffffffu, b3 <= th1);
#pragma unroll
                for (int e = 0; e < 8; e++) {
                    unsigned qb = (bal[e] >> (lane & 28)) & 0xFu;
                    const int i = ((e & 3) >= 2) ? R1 : R0;
                    const int tt = (e < 4) ? tA : tB;
                    while (qb) {
                        int b = __ffs((int)qb) - 1;
                        qb &= qb - 1;
                        int j = k0 + 8 * tt + 2 * b + (e & 1);
                        // exact fp32 dot, quad-cooperative (16 dims/lane)
                        const float* qg = &g_q[(size_t)i * DMODEL + hb + t4 * 16];
                        const float* kg = &g_k[(size_t)j * DMODEL + hb + t4 * 16];
                        float s = 0.f;
#pragma unroll
                        for (int c4 = 0; c4 < 4; c4++) {
                            float4 qv = *(const float4*)&qg[c4 * 4];
                            float4 kv = *(const float4*)&kg[c4 * 4];
                            s = fmaf(qv.x, kv.x, s);
                            s = fmaf(qv.y, kv.y, s);
                            s = fmaf(qv.z, kv.z, s);
                            s = fmaf(qv.w, kv.w, s);
                        }
                        s += __shfl_xor_sync(qmask, s, 1);
                        s += __shfl_xor_sync(qmask, s, 2);
                        float y = s * 0.125f;
                        if (!(j == i || j == i - 1)) y = y * -1000000000.0f;
                        const float* vg = &g_v[(size_t)j * DMODEL + hb + t4 * 16];
                        if ((e & 3) < 2) {
                            if (y > rmax0) {
                                float scl = expf(rmax0 - y);
                                rsum0 *= scl;
#pragma unroll
                                for (int d = 0; d < 16; d++) acc0[d] *= scl;
                                rmax0 = y;
                            }
                            float p = expf(y - rmax0);
                            rsum0 += p;
#pragma unroll
                            for (int c4 = 0; c4 < 4; c4++) {
                                float4 vv = *(const float4*)&vg[c4 * 4];
                                acc0[c4 * 4 + 0] = fmaf(p, vv.x, acc0[c4 * 4 + 0]);
                                acc0[c4 * 4 + 1] = fmaf(p, vv.y, acc0[c4 * 4 + 1]);
                                acc0[c4 * 4 + 2] = fmaf(p, vv.z, acc0[c4 * 4 + 2]);
                                acc0[c4 * 4 + 3] = fmaf(p, vv.w, acc0[c4 * 4 + 3]);
                            }
                        } else {
                            if (y > rmax1) {
                                float scl = expf(rmax1 - y);
                                rsum1 *= scl;
#pragma unroll
                                for (int d = 0; d < 16; d++) acc1[d] *= scl;
                                rmax1 = y;
                            }
                            float p = expf(y - rmax1);
                            rsum1 += p;
#pragma unroll
                            for (int c4 = 0; c4 < 4; c4++) {
                                float4 vv = *(const float4*)&vg[c4 * 4];
                                acc1[c4 * 4 + 0] = fmaf(p, vv.x, acc1[c4 * 4 + 0]);
                                acc1[c4 * 4 + 1] = fmaf(p, vv.y, acc1[c4 * 4 + 1]);
                                acc1[c4 * 4 + 2] = fmaf(p, vv.z, acc1[c4 * 4 + 2]);
                                acc1[c4 * 4 + 3] = fmaf(p, vv.w, acc1[c4 * 4 + 3]);
                            }
                        }
                    }
                }
            }
        }
        // tighten run-min across the quad (converged point, full-mask shfl)
        run0 = fminf(run0, __shfl_xor_sync(0xffffffffu, run0, 1));
        run0 = fminf(run0, __shfl_xor_sync(0xffffffffu, run0, 2));
        run1 = fminf(run1, __shfl_xor_sync(0xffffffffu, run1, 1));
        run1 = fminf(run1, __shfl_xor_sync(0xffffffffu, run1, 2));
    }

    // epilogue: normalize and store
    {
        float inv0 = 1.f / rsum0;
        float inv1 = 1.f / rsum1;
        float* o0 = &g_attn[(size_t)R0 * DMODEL + hb + t4 * 16];
        float* o1 = &g_attn[(size_t)R1 * DMODEL + hb + t4 * 16];
#pragma unroll
        for (int c4 = 0; c4 < 4; c4++) {
            float4 a = {acc0[c4 * 4 + 0] * inv0, acc0[c4 * 4 + 1] * inv0,
                        acc0[c4 * 4 + 2] * inv0, acc0[c4 * 4 + 3] * inv0};
            float4 b = {acc1[c4 * 4 + 0] * inv1, acc1[c4 * 4 + 1] * inv1,
                        acc1[c4 * 4 + 2] * inv1, acc1[c4 * 4 + 3] * inv1};
            *(float4*)&o0[c4 * 4] = a;
            *(float4*)&o1[c4 * 4] = b;
        }
    }
}

// ---------------------------------------------------------------------------
// K3: out[4096,64] = g_attn[4096,1024] @ Wm[1024,64] + bm  (verbatim)
// ---------------------------------------------------------------------------
__global__ __launch_bounds__(256) void sgemm_out(
    const float* __restrict__ A, const float* __restrict__ B,
    const float* __restrict__ bias, float* __restrict__ C)
{
    __shared__ float As[16][64];
    __shared__ float Bs[16][64];

    const int tid = threadIdx.x;
    const int tx = tid & 15, ty = tid >> 4;
    const int by = blockIdx.x * 64;

    const int ar = tid >> 2;
    const int ac = (tid & 3) * 4;
    const int br = tid >> 4;
    const int bc = (tid & 15) * 4;

    float acc[4][4];
#pragma unroll
    for (int i = 0; i < 4; i++)
#pragma unroll
        for (int j = 0; j < 4; j++) acc[i][j] = 0.f;

    for (int k0 = 0; k0 < DMODEL; k0 += 16) {
        float4 av = *(const float4*)&A[(size_t)(by + ar) * DMODEL + k0 + ac];
        float4 bv = *(const float4*)&B[(size_t)(k0 + br) * 64 + bc];
        As[ac + 0][ar] = av.x;
        As[ac + 1][ar] = av.y;
        As[ac + 2][ar] = av.z;
        As[ac + 3][ar] = av.w;
        *(float4*)&Bs[br][bc] = bv;
        __syncthreads();
#pragma unroll
        for (int kk = 0; kk < 16; kk++) {
            float4 a = *(const float4*)&As[kk][ty * 4];
            float4 b = *(const float4*)&Bs[kk][tx * 4];
            float av4[4] = {a.x, a.y, a.z, a.w};
            float bv4[4] = {b.x, b.y, b.z, b.w};
#pragma unroll
            for (int i = 0; i < 4; i++)
#pragma unroll
                for (int j = 0; j < 4; j++)
                    acc[i][j] = fmaf(av4[i], bv4[j], acc[i][j]);
        }
        __syncthreads();
    }

#pragma unroll
    for (int i = 0; i < 4; i++) {
        int row = by + ty * 4 + i;
        float4 o;
        o.x = acc[i][0] + bias[tx * 4 + 0];
        o.y = acc[i][1] + bias[tx * 4 + 1];
        o.z = acc[i][2] + bias[tx * 4 + 2];
        o.w = acc[i][3] + bias[tx * 4 + 3];
        *(float4*)&C[(size_t)row * 64 + tx * 4] = o;
    }
}

// ---------------------------------------------------------------------------
// kernel_launch
// ---------------------------------------------------------------------------
extern "C" void kernel_launch(void* const* d_in, const int* in_sizes, int n_in,
                              void* d_out, int out_size)
{
    const float* X  = (const float*)d_in[0];
    const float* Wq = (const float*)d_in[2];
    const float* bq = (const float*)d_in[3];
    const float* Wk = (const float*)d_in[4];
    const float* bk = (const float*)d_in[5];
    const float* Wv = (const float*)d_in[6];
    const float* bv = (const float*)d_in[7];
    const float* Wm = (const float*)d_in[8];
    const float* bm = (const float*)d_in[9];
    float* out = (float*)d_out;

    float *qp, *kp, *vp, *ap;
    cudaGetSymbolAddress((void**)&qp, g_q);
    cudaGetSymbolAddress((void**)&kp, g_k);
    cudaGetSymbolAddress((void**)&vp, g_v);
    cudaGetSymbolAddress((void**)&ap, g_attn);

    sgemm_qkv<<<dim3(24, 32), 256>>>(X, Wq, Wk, Wv, bq, bk, bv, qp, kp, vp);

    cudaFuncSetAttribute(attn_kernel,
                         cudaFuncAttributeMaxDynamicSharedMemorySize,
                         ATT_SMEM_BYTES);
    attn_kernel<<<dim3(SQ / 128, NH), 256, ATT_SMEM_BYTES>>>();

    sgemm_out<<<SQ / 64, 256>>>(ap, Wm, bm, out);
}